// round 6
// baseline (speedup 1.0000x reference)
#include <cuda_runtime.h>
#include <cuda_fp16.h>

#define NN 50000         // n_node
#define KP 8             // k_path
#define LP 6             // l_path
#define DN 64            // d_node
#define DP 128           // d_path
#define NE 1600000       // n_edge
#define KTOT 320         // (LP-1)*DN
#define NKTOT 400000     // NN*KP
#define CTA_N 128        // nk columns per CTA

#define AS_STRIDE 328    // halves per A_s row (320 + 8 pad)
#define BS_STRIDE 72     // halves per B_s row (64 + 8 pad)

// SMEM layout (bytes):
//   A_s  : half[128*328]   @ 0       (83,968 B)  } C_s float[128*132] reuses this
//   B_s  : half[2][128*72] @ 83968   (36,864 B)
//   idx_s: int[6][128]     @ 120832  ( 3,072 B)
//   w_s  : float[5][128]   @ 123904  ( 2,560 B)
#define SMEM_BYTES 126464

__device__ __half g_feat16[(size_t)(NN + 1) * DN];  // 6.4 MB, L2-resident; row NN = zeros
__device__ __half g_W16[DP * KTOT];                 // 80 KB
__device__ int g_is64;

// ---------------------------------------------------------------------------
__global__ void detect_dtype(const unsigned int* __restrict__ paths_raw) {
  unsigned v = paths_raw[threadIdx.x * 2 + 1];
  unsigned any = __ballot_sync(0xFFFFFFFFu, v != 0u);
  if (threadIdx.x == 0) g_is64 = (any == 0u) ? 1 : 0;
}

// Convert feat and W to fp16 tables (grid-stride).
__global__ void prep_fp16(const float* __restrict__ feat, const float* __restrict__ W) {
  const size_t stride = (size_t)gridDim.x * blockDim.x;
  size_t i = (size_t)blockIdx.x * blockDim.x + threadIdx.x;
  const size_t featTot = (size_t)(NN + 1) * DN;
  for (size_t j = i; j < featTot; j += stride) {
    float v = (j < (size_t)NN * DN) ? feat[j] : 0.f;
    g_feat16[j] = __float2half_rn(v);
  }
  for (size_t j = i; j < (size_t)DP * KTOT; j += stride)
    g_W16[j] = __float2half_rn(W[j]);
}

__device__ __forceinline__ unsigned hfma2u(unsigned nx, unsigned w2, unsigned cur) {
  __half2 r = __hfma2(*(__half2*)&nx, *(__half2*)&w2, *(__half2*)&cur);
  return *(unsigned*)&r;
}

__device__ __forceinline__ uint4 hfma2x4(uint4 nx, unsigned w2, uint4 cur) {
  uint4 o;
  o.x = hfma2u(nx.x, w2, cur.x);
  o.y = hfma2u(nx.y, w2, cur.y);
  o.z = hfma2u(nx.z, w2, cur.z);
  o.w = hfma2u(nx.w, w2, cur.w);
  return o;
}

// ---------------------------------------------------------------------------
// Fused kernel: per CTA, 128 nk columns. D[128 d, 128 nk] = W16 @ combined.
// combined built per-l (K chunks of 64) from gathered feat16 rows.
// ---------------------------------------------------------------------------
__global__ void __launch_bounds__(256, 1) fused_path(
    const void* __restrict__ paths_v,
    const void* __restrict__ eids_v,
    const float* __restrict__ weight,
    float* __restrict__ out) {
  extern __shared__ char sm[];
  __half* A_s  = (__half*)sm;                     // [128][328]
  __half* B_s  = (__half*)(sm + 83968);           // [2][128][72]
  int*    idx_s = (int*)(sm + 120832);            // [6][128]
  float*  w_s  = (float*)(sm + 123904);           // [5][128]

  const int t = threadIdx.x;
  const int nk0 = blockIdx.x * CTA_N;

  // ---- load W16 -> A_s (padded) ----
  {
    const uint4* Wg = (const uint4*)g_W16;        // 8 halves per uint4, 40 per d-row
#pragma unroll
    for (int i = 0; i < 20; i++) {
      int c = t + 256 * i;                        // 5120 chunks total
      int d = c / 40;
      int kc = (c % 40) * 8;
      uint4 v = Wg[c];
      *(uint4*)(A_s + d * AS_STRIDE + kc) = v;
    }
  }

  // ---- stage clamped indices + edge weights ----
  if (t < CTA_N) {
    if (g_is64) {
      const long long* p = (const long long*)paths_v + (size_t)(nk0 + t) * LP;
      const long long* e = (const long long*)eids_v + (size_t)(nk0 + t) * (LP - 1);
#pragma unroll
      for (int i = 0; i < LP; i++) {
        long long v = p[i];
        v = v < 0 ? 0 : (v > NN ? NN : v);
        idx_s[i * CTA_N + t] = (int)v;
      }
#pragma unroll
      for (int i = 0; i < LP - 1; i++) {
        long long ev = e[i];
        ev = ev < 0 ? 0 : (ev > NE - 1 ? NE - 1 : ev);
        w_s[i * CTA_N + t] = weight[ev];
      }
    } else {
      const int* p = (const int*)paths_v + (size_t)(nk0 + t) * LP;
      const int* e = (const int*)eids_v + (size_t)(nk0 + t) * (LP - 1);
#pragma unroll
      for (int i = 0; i < LP; i++) {
        int v = p[i];
        v = v < 0 ? 0 : (v > NN ? NN : v);
        idx_s[i * CTA_N + t] = v;
      }
#pragma unroll
      for (int i = 0; i < LP - 1; i++) {
        int ev = e[i];
        ev = ev < 0 ? 0 : (ev > NE - 1 ? NE - 1 : ev);
        w_s[i * CTA_N + t] = weight[ev];
      }
    }
  }
  __syncthreads();

  // ---- mma thread coords ----
  const int lane = t & 31;
  const int wid = t >> 5;
  const int m0 = (wid >> 1) * 32;   // 4 warps along M (d)
  const int n0 = (wid & 1) * 64;    // 2 warps along N (nk)
  const int grp = lane >> 2;        // groupID 0..7
  const int tig = lane & 3;         // threadID_in_group

  float acc[2][8][4];
#pragma unroll
  for (int a = 0; a < 2; a++)
#pragma unroll
    for (int b = 0; b < 8; b++)
#pragma unroll
      for (int c = 0; c < 4; c++) acc[a][b][c] = 0.f;

  // ---- gather state: this thread owns halves [hh*32, hh*32+32) of column col
  //      (32 halves = 4 x uint4) ----
  const int col = t >> 1;
  const int hh = t & 1;
  uint4 cur[4];
  {
    const uint4* fr = (const uint4*)(g_feat16 + (size_t)idx_s[col] * DN + hh * 32);
#pragma unroll
    for (int q = 0; q < 4; q++) cur[q] = fr[q];
  }

  for (int l = 0; l < 5; l++) {
    __half* Bb = B_s + (l & 1) * (CTA_N * BS_STRIDE);

    // ---- build combined_l into B_s[n][k] (k contiguous) ----
    {
      const uint4* fr =
          (const uint4*)(g_feat16 + (size_t)idx_s[(l + 1) * CTA_N + col] * DN + hh * 32);
      uint4 nx[4];
#pragma unroll
      for (int q = 0; q < 4; q++) nx[q] = fr[q];
      __half2 w2h = __float2half2_rn(w_s[l * CTA_N + col]);
      unsigned w2 = *(unsigned*)&w2h;
      uint4* bp = (uint4*)(Bb + col * BS_STRIDE + hh * 32);
#pragma unroll
      for (int q = 0; q < 4; q++) {
        bp[q] = hfma2x4(nx[q], w2, cur[q]);
        cur[q] = nx[q];
      }
    }
    __syncthreads();   // B_l visible; double buffer keeps one sync per iter safe

    // ---- mma: warp tile 32(M) x 64(N), K=64 in 4 steps of 16 ----
    const __half* Acol = A_s + l * 64;
#pragma unroll
    for (int ks = 0; ks < 4; ks++) {
      unsigned afr[2][4];
#pragma unroll
      for (int mt = 0; mt < 2; mt++) {
        const __half* ap = Acol + (size_t)(m0 + mt * 16 + grp) * AS_STRIDE + ks * 16 + tig * 2;
        afr[mt][0] = *(const unsigned*)(ap);                       // (row,      k)
        afr[mt][1] = *(const unsigned*)(ap + 8 * AS_STRIDE);       // (row+8,    k)
        afr[mt][2] = *(const unsigned*)(ap + 8);                   // (row,      k+8)
        afr[mt][3] = *(const unsigned*)(ap + 8 * AS_STRIDE + 8);   // (row+8,    k+8)
      }
#pragma unroll
      for (int nt = 0; nt < 8; nt++) {
        const __half* bp = Bb + (size_t)(n0 + nt * 8 + grp) * BS_STRIDE + ks * 16 + tig * 2;
        unsigned b0 = *(const unsigned*)(bp);       // (k,   n)
        unsigned b1 = *(const unsigned*)(bp + 8);   // (k+8, n)
#pragma unroll
        for (int mt = 0; mt < 2; mt++)
          asm volatile(
              "mma.sync.aligned.m16n8k16.row.col.f32.f16.f16.f32 "
              "{%0,%1,%2,%3}, {%4,%5,%6,%7}, {%8,%9}, {%0,%1,%2,%3};"
              : "+f"(acc[mt][nt][0]), "+f"(acc[mt][nt][1]),
                "+f"(acc[mt][nt][2]), "+f"(acc[mt][nt][3])
              : "r"(afr[mt][0]), "r"(afr[mt][1]), "r"(afr[mt][2]), "r"(afr[mt][3]),
                "r"(b0), "r"(b1));
      }
    }
  }

  // ---- epilogue: stage C[nk][d] in smem (reuse A_s region), coalesced writes ----
  __syncthreads();
  float* C_s = (float*)sm;   // [128 nk][132]
#pragma unroll
  for (int mt = 0; mt < 2; mt++)
#pragma unroll
    for (int nt = 0; nt < 8; nt++) {
      int r = m0 + mt * 16 + grp;        // d
      int c = n0 + nt * 8 + tig * 2;     // nk
      C_s[(c) * 132 + r] = acc[mt][nt][0];
      C_s[(c + 1) * 132 + r] = acc[mt][nt][1];
      C_s[(c) * 132 + r + 8] = acc[mt][nt][2];
      C_s[(c + 1) * 132 + r + 8] = acc[mt][nt][3];
    }
  __syncthreads();
  {
    int n = t >> 1, h = t & 1;
    const float* src = C_s + n * 132 + h * 64;
    float* dst = out + (size_t)(nk0 + n) * DP + h * 64;
#pragma unroll
    for (int j = 0; j < 16; j++)
      *(float4*)(dst + j * 4) = *(const float4*)(src + j * 4);
  }
}

// ---------------------------------------------------------------------------
// Launch. Inputs identified BY ELEMENT COUNT (all five distinct):
//   feat=3,200,000 f32 | weight=1,600,000 f32 | W=40,960 f32
//   paths=2,400,000 (i32/i64) | edge_ids=2,000,000 (i32/i64)
// ---------------------------------------------------------------------------
extern "C" void kernel_launch(void* const* d_in, const int* in_sizes, int n_in,
                              void* d_out, int out_size) {
  const float* feat = 0;
  const float* weight = 0;
  const float* W = 0;
  const void* paths = 0;
  const void* eids = 0;

  for (int i = 0; i < n_in; i++) {
    switch (in_sizes[i]) {
      case 3200000: feat   = (const float*)d_in[i]; break;
      case 1600000: weight = (const float*)d_in[i]; break;
      case 40960:   W      = (const float*)d_in[i]; break;
      case 2400000: paths  = d_in[i];               break;
      case 2000000: eids   = d_in[i];               break;
      default: break;
    }
  }
  if (!feat || !weight || !W || !paths || !eids) return;

  float* out = (float*)d_out;

  cudaFuncSetAttribute(fused_path, cudaFuncAttributeMaxDynamicSharedMemorySize,
                       SMEM_BYTES);

  detect_dtype<<<1, 32>>>((const unsigned int*)paths);
  prep_fp16<<<512, 256>>>(feat, W);
  fused_path<<<NKTOT / CTA_N, 256, SMEM_BYTES>>>(paths, eids, weight, out);
}

// round 7
// speedup vs baseline: 1.6596x; 1.6596x over previous
#include <cuda_runtime.h>
#include <cuda_fp16.h>

#define NN 50000         // n_node
#define KP 8             // k_path
#define LP 6             // l_path
#define DN 64            // d_node
#define DP 128           // d_path
#define NE 1600000       // n_edge
#define PROJ_COLS 640    // (LP-1) * DP

// fp16 proj table (64 MB, L2-resident). proj[node][l*128+d]; row NN = zeros.
__device__ __half g_proj[(size_t)(NN + 1) * PROJ_COLS];
__device__ int g_is64;

// ---------------------------------------------------------------------------
__global__ void detect_dtype(const unsigned int* __restrict__ paths_raw) {
  unsigned v = paths_raw[threadIdx.x * 2 + 1];
  unsigned any = __ballot_sync(0xFFFFFFFFu, v != 0u);
  if (threadIdx.x == 0) g_is64 = (any == 0u) ? 1 : 0;
}

// ---------------------------------------------------------------------------
// Phase 1 (tensor-core): proj[node][l*128+d] = sum_c feat16[node,c] * W16[d, l*64+c]
// Per CTA: 128 nodes (M) x 128 d (N), K=64, one l block (blockIdx.y).
// 256 threads = 8 warps: 4 along M x 2 along N; warp tile 32M x 64N.
// ---------------------------------------------------------------------------
#define TS 72   // smem row stride in halves (64 + 8 pad) -> conflict-free frags

__global__ void __launch_bounds__(256, 2) phase1_mma(
    const float* __restrict__ feat, const float* __restrict__ W) {
  __shared__ __half As[128 * TS];   // [node][c]
  __shared__ __half Bs[128 * TS];   // [d][c]

  const int t = threadIdx.x;
  const int node0 = blockIdx.x * 128;
  const int l = blockIdx.y;

  // ---- load + convert A tile: 128 nodes x 64 c (2048 float4, 8 per thread) ----
#pragma unroll
  for (int i = 0; i < 8; i++) {
    int f4 = t + 256 * i;
    int row = f4 >> 4;              // local node row 0..127
    int c4 = (f4 & 15) * 4;
    int node = node0 + row;
    float4 v = make_float4(0.f, 0.f, 0.f, 0.f);
    if (node < NN) v = *(const float4*)(feat + (size_t)node * DN + c4);
    __half2 h0 = __floats2half2_rn(v.x, v.y);
    __half2 h1 = __floats2half2_rn(v.z, v.w);
    uint2 pk;
    pk.x = *(unsigned*)&h0;
    pk.y = *(unsigned*)&h1;
    *(uint2*)(As + row * TS + c4) = pk;
  }
  // ---- load + convert B tile: 128 d x 64 c from W[d][320] slice [l*64, l*64+64) ----
#pragma unroll
  for (int i = 0; i < 8; i++) {
    int f4 = t + 256 * i;
    int d = f4 >> 4;
    int c4 = (f4 & 15) * 4;
    float4 v = *(const float4*)(W + (size_t)d * 320 + l * 64 + c4);
    __half2 h0 = __floats2half2_rn(v.x, v.y);
    __half2 h1 = __floats2half2_rn(v.z, v.w);
    uint2 pk;
    pk.x = *(unsigned*)&h0;
    pk.y = *(unsigned*)&h1;
    *(uint2*)(Bs + d * TS + c4) = pk;
  }
  __syncthreads();

  const int lane = t & 31;
  const int wid = t >> 5;
  const int m0 = (wid >> 1) * 32;   // node dim
  const int n0 = (wid & 1) * 64;    // d dim
  const int grp = lane >> 2;
  const int tig = lane & 3;

  float acc[2][8][4];
#pragma unroll
  for (int a = 0; a < 2; a++)
#pragma unroll
    for (int b = 0; b < 8; b++)
#pragma unroll
      for (int c = 0; c < 4; c++) acc[a][b][c] = 0.f;

#pragma unroll
  for (int ks = 0; ks < 4; ks++) {
    unsigned afr[2][4];
#pragma unroll
    for (int mt = 0; mt < 2; mt++) {
      const __half* ap = As + (size_t)(m0 + mt * 16 + grp) * TS + ks * 16 + tig * 2;
      afr[mt][0] = *(const unsigned*)(ap);
      afr[mt][1] = *(const unsigned*)(ap + 8 * TS);
      afr[mt][2] = *(const unsigned*)(ap + 8);
      afr[mt][3] = *(const unsigned*)(ap + 8 * TS + 8);
    }
#pragma unroll
    for (int nt = 0; nt < 8; nt++) {
      const __half* bp = Bs + (size_t)(n0 + nt * 8 + grp) * TS + ks * 16 + tig * 2;
      unsigned b0 = *(const unsigned*)(bp);
      unsigned b1 = *(const unsigned*)(bp + 8);
#pragma unroll
      for (int mt = 0; mt < 2; mt++)
        asm volatile(
            "mma.sync.aligned.m16n8k16.row.col.f32.f16.f16.f32 "
            "{%0,%1,%2,%3}, {%4,%5,%6,%7}, {%8,%9}, {%0,%1,%2,%3};"
            : "+f"(acc[mt][nt][0]), "+f"(acc[mt][nt][1]),
              "+f"(acc[mt][nt][2]), "+f"(acc[mt][nt][3])
            : "r"(afr[mt][0]), "r"(afr[mt][1]), "r"(afr[mt][2]), "r"(afr[mt][3]),
              "r"(b0), "r"(b1));
    }
  }

  // ---- epilogue: half2 stores straight to the proj table ----
#pragma unroll
  for (int mt = 0; mt < 2; mt++) {
    int nodeA = node0 + m0 + mt * 16 + grp;
    int nodeB = nodeA + 8;
#pragma unroll
    for (int nt = 0; nt < 8; nt++) {
      int d = n0 + nt * 8 + tig * 2;
      if (nodeA <= NN) {
        __half2 h = __floats2half2_rn(acc[mt][nt][0], acc[mt][nt][1]);
        *(__half2*)(g_proj + (size_t)nodeA * PROJ_COLS + l * DP + d) = h;
      }
      if (nodeB <= NN) {
        __half2 h = __floats2half2_rn(acc[mt][nt][2], acc[mt][nt][3]);
        *(__half2*)(g_proj + (size_t)nodeB * PROJ_COLS + l * DP + d) = h;
      }
    }
  }
}

// ---------------------------------------------------------------------------
// Phase 2 (identical to the 250 µs R4 version): one warp per (n,k).
// ---------------------------------------------------------------------------
__global__ void __launch_bounds__(256) phase2_gather(
    const void* __restrict__ paths_v,
    const void* __restrict__ eids_v,
    const float* __restrict__ weight,
    float* __restrict__ out) {
  const long long gw = (((long long)blockIdx.x * blockDim.x) + threadIdx.x) >> 5;
  const int lane = threadIdx.x & 31;
  if (gw >= (long long)NN * KP) return;

  const int is64 = g_is64;

  long long idx[LP];
  float w[LP - 1];
  if (is64) {
    const long long* p = (const long long*)paths_v + gw * LP;
    const long long* e = (const long long*)eids_v + gw * (LP - 1);
#pragma unroll
    for (int i = 0; i < LP; i++) {
      long long v = p[i];
      idx[i] = v < 0 ? 0 : (v > NN ? NN : v);
    }
#pragma unroll
    for (int i = 0; i < LP - 1; i++) {
      long long ev = e[i];
      ev = ev < 0 ? 0 : (ev > NE - 1 ? NE - 1 : ev);
      w[i] = weight[ev];
    }
  } else {
    const int* p = (const int*)paths_v + gw * LP;
    const int* e = (const int*)eids_v + gw * (LP - 1);
#pragma unroll
    for (int i = 0; i < LP; i++) {
      int v = p[i];
      idx[i] = v < 0 ? 0 : (v > NN ? NN : v);
    }
#pragma unroll
    for (int i = 0; i < LP - 1; i++) {
      int ev = e[i];
      ev = ev < 0 ? 0 : (ev > NE - 1 ? NE - 1 : ev);
      w[i] = weight[ev];
    }
  }

  const int col = lane * 4;
  uint2 ra[LP - 1], rb[LP - 1];
#pragma unroll
  for (int i = 0; i < LP - 1; i++) {
    ra[i] = *(const uint2*)(g_proj + (size_t)idx[i] * PROJ_COLS + i * DP + col);
    rb[i] = *(const uint2*)(g_proj + (size_t)idx[i + 1] * PROJ_COLS + i * DP + col);
  }

  float4 acc = make_float4(0.f, 0.f, 0.f, 0.f);
#pragma unroll
  for (int i = 0; i < LP - 1; i++) {
    float2 a01 = __half22float2(*(const __half2*)&ra[i].x);
    float2 a23 = __half22float2(*(const __half2*)&ra[i].y);
    float2 b01 = __half22float2(*(const __half2*)&rb[i].x);
    float2 b23 = __half22float2(*(const __half2*)&rb[i].y);
    acc.x += a01.x + w[i] * b01.x;
    acc.y += a01.y + w[i] * b01.y;
    acc.z += a23.x + w[i] * b23.x;
    acc.w += a23.y + w[i] * b23.y;
  }
  *(float4*)(out + gw * DP + col) = acc;
}

// ---------------------------------------------------------------------------
// Launch. Inputs identified BY ELEMENT COUNT (all five distinct):
//   feat=3,200,000 f32 | weight=1,600,000 f32 | W=40,960 f32
//   paths=2,400,000 (i32/i64) | edge_ids=2,000,000 (i32/i64)
// ---------------------------------------------------------------------------
extern "C" void kernel_launch(void* const* d_in, const int* in_sizes, int n_in,
                              void* d_out, int out_size) {
  const float* feat = 0;
  const float* weight = 0;
  const float* W = 0;
  const void* paths = 0;
  const void* eids = 0;

  for (int i = 0; i < n_in; i++) {
    switch (in_sizes[i]) {
      case 3200000: feat   = (const float*)d_in[i]; break;
      case 1600000: weight = (const float*)d_in[i]; break;
      case 40960:   W      = (const float*)d_in[i]; break;
      case 2400000: paths  = d_in[i];               break;
      case 2000000: eids   = d_in[i];               break;
      default: break;
    }
  }
  if (!feat || !weight || !W || !paths || !eids) return;

  float* out = (float*)d_out;

  detect_dtype<<<1, 32>>>((const unsigned int*)paths);

  dim3 g1((NN + 1 + 127) / 128, 5);   // 391 x 5 CTAs, one l block per y
  phase1_mma<<<g1, 256>>>(feat, W);

  long long warps = (long long)NN * KP;               // 400,000
  int blocks = (int)((warps * 32 + 255) / 256);       // 50,000
  phase2_gather<<<blocks, 256>>>(paths, eids, weight, out);
}

// round 9
// speedup vs baseline: 1.7207x; 1.0368x over previous
#include <cuda_runtime.h>
#include <cuda_fp16.h>

#define NN 50000         // n_node
#define KP 8             // k_path
#define LP 6             // l_path
#define DN 64            // d_node
#define DP 128           // d_path
#define NE 1600000       // n_edge
#define PROJ_COLS 640    // (LP-1) * DP

// fp16 proj table (64 MB, L2-resident). proj[node][l*128+d]; row NN = zeros.
__device__ __half g_proj[(size_t)(NN + 1) * PROJ_COLS];
__device__ int g_is64;

// ---------------------------------------------------------------------------
// Phase 1 (tensor-core): proj[node][l*128+d] = sum_c feat16[node,c] * W16[d, l*64+c]
// Per CTA: 128 nodes (M) x 128 d (N), K=64, one l block (blockIdx.y).
// Block (0,0) warp 0 additionally sniffs the index dtype into g_is64.
// ---------------------------------------------------------------------------
#define TS 72   // smem row stride in halves (64 + 8 pad) -> conflict-free frags

__global__ void __launch_bounds__(256, 2) phase1_mma(
    const float* __restrict__ feat, const float* __restrict__ W,
    const unsigned int* __restrict__ paths_raw) {
  __shared__ __half As[128 * TS];   // [node][c]
  __shared__ __half Bs[128 * TS];   // [d][c]

  const int t = threadIdx.x;
  const int node0 = blockIdx.x * 128;
  const int l = blockIdx.y;

  // ---- dtype sniff (one warp, one block): int64 data has all-zero high words ----
  if (blockIdx.x == 0 && blockIdx.y == 0 && t < 32) {
    unsigned v = paths_raw[t * 2 + 1];
    unsigned any = __ballot_sync(0xFFFFFFFFu, v != 0u);
    if (t == 0) g_is64 = (any == 0u) ? 1 : 0;
  }

  // ---- load + convert A tile: 128 nodes x 64 c (2048 float4, 8 per thread) ----
#pragma unroll
  for (int i = 0; i < 8; i++) {
    int f4 = t + 256 * i;
    int row = f4 >> 4;              // local node row 0..127
    int c4 = (f4 & 15) * 4;
    int node = node0 + row;
    float4 v = make_float4(0.f, 0.f, 0.f, 0.f);
    if (node < NN) v = *(const float4*)(feat + (size_t)node * DN + c4);
    __half2 h0 = __floats2half2_rn(v.x, v.y);
    __half2 h1 = __floats2half2_rn(v.z, v.w);
    uint2 pk;
    pk.x = *(unsigned*)&h0;
    pk.y = *(unsigned*)&h1;
    *(uint2*)(As + row * TS + c4) = pk;
  }
  // ---- load + convert B tile: 128 d x 64 c from W[d][320] slice [l*64, l*64+64) ----
#pragma unroll
  for (int i = 0; i < 8; i++) {
    int f4 = t + 256 * i;
    int d = f4 >> 4;
    int c4 = (f4 & 15) * 4;
    float4 v = *(const float4*)(W + (size_t)d * 320 + l * 64 + c4);
    __half2 h0 = __floats2half2_rn(v.x, v.y);
    __half2 h1 = __floats2half2_rn(v.z, v.w);
    uint2 pk;
    pk.x = *(unsigned*)&h0;
    pk.y = *(unsigned*)&h1;
    *(uint2*)(Bs + d * TS + c4) = pk;
  }
  __syncthreads();

  const int lane = t & 31;
  const int wid = t >> 5;
  const int m0 = (wid >> 1) * 32;   // node dim
  const int n0 = (wid & 1) * 64;    // d dim
  const int grp = lane >> 2;
  const int tig = lane & 3;

  float acc[2][8][4];
#pragma unroll
  for (int a = 0; a < 2; a++)
#pragma unroll
    for (int b = 0; b < 8; b++)
#pragma unroll
      for (int c = 0; c < 4; c++) acc[a][b][c] = 0.f;

#pragma unroll
  for (int ks = 0; ks < 4; ks++) {
    unsigned afr[2][4];
#pragma unroll
    for (int mt = 0; mt < 2; mt++) {
      const __half* ap = As + (size_t)(m0 + mt * 16 + grp) * TS + ks * 16 + tig * 2;
      afr[mt][0] = *(const unsigned*)(ap);
      afr[mt][1] = *(const unsigned*)(ap + 8 * TS);
      afr[mt][2] = *(const unsigned*)(ap + 8);
      afr[mt][3] = *(const unsigned*)(ap + 8 * TS + 8);
    }
#pragma unroll
    for (int nt = 0; nt < 8; nt++) {
      const __half* bp = Bs + (size_t)(n0 + nt * 8 + grp) * TS + ks * 16 + tig * 2;
      unsigned b0 = *(const unsigned*)(bp);
      unsigned b1 = *(const unsigned*)(bp + 8);
#pragma unroll
      for (int mt = 0; mt < 2; mt++)
        asm volatile(
            "mma.sync.aligned.m16n8k16.row.col.f32.f16.f16.f32 "
            "{%0,%1,%2,%3}, {%4,%5,%6,%7}, {%8,%9}, {%0,%1,%2,%3};"
            : "+f"(acc[mt][nt][0]), "+f"(acc[mt][nt][1]),
              "+f"(acc[mt][nt][2]), "+f"(acc[mt][nt][3])
            : "r"(afr[mt][0]), "r"(afr[mt][1]), "r"(afr[mt][2]), "r"(afr[mt][3]),
              "r"(b0), "r"(b1));
    }
  }

  // ---- epilogue: half2 stores straight to the proj table (normal caching:
  //      we WANT these lines resident in L2 for phase 2) ----
#pragma unroll
  for (int mt = 0; mt < 2; mt++) {
    int nodeA = node0 + m0 + mt * 16 + grp;
    int nodeB = nodeA + 8;
#pragma unroll
    for (int nt = 0; nt < 8; nt++) {
      int d = n0 + nt * 8 + tig * 2;
      if (nodeA <= NN) {
        __half2 h = __floats2half2_rn(acc[mt][nt][0], acc[mt][nt][1]);
        *(__half2*)(g_proj + (size_t)nodeA * PROJ_COLS + l * DP + d) = h;
      }
      if (nodeB <= NN) {
        __half2 h = __floats2half2_rn(acc[mt][nt][2], acc[mt][nt][3]);
        *(__half2*)(g_proj + (size_t)nodeB * PROJ_COLS + l * DP + d) = h;
      }
    }
  }
}

// ---------------------------------------------------------------------------
// Phase 2: one warp per (n,k). Gathers via read-only path; output via
// streaming (evict-first) stores so the 205 MB of writes don't evict the
// proj table from L2.
// ---------------------------------------------------------------------------
__global__ void __launch_bounds__(256) phase2_gather(
    const void* __restrict__ paths_v,
    const void* __restrict__ eids_v,
    const float* __restrict__ weight,
    float* __restrict__ out) {
  const long long gw = (((long long)blockIdx.x * blockDim.x) + threadIdx.x) >> 5;
  const int lane = threadIdx.x & 31;
  if (gw >= (long long)NN * KP) return;

  const int is64 = g_is64;

  long long idx[LP];
  float w[LP - 1];
  if (is64) {
    const long long* p = (const long long*)paths_v + gw * LP;
    const long long* e = (const long long*)eids_v + gw * (LP - 1);
#pragma unroll
    for (int i = 0; i < LP; i++) {
      long long v = __ldg(p + i);
      idx[i] = v < 0 ? 0 : (v > NN ? NN : v);
    }
#pragma unroll
    for (int i = 0; i < LP - 1; i++) {
      long long ev = __ldg(e + i);
      ev = ev < 0 ? 0 : (ev > NE - 1 ? NE - 1 : ev);
      w[i] = __ldg(weight + ev);
    }
  } else {
    const int* p = (const int*)paths_v + gw * LP;
    const int* e = (const int*)eids_v + gw * (LP - 1);
#pragma unroll
    for (int i = 0; i < LP; i++) {
      int v = __ldg(p + i);
      idx[i] = v < 0 ? 0 : (v > NN ? NN : v);
    }
#pragma unroll
    for (int i = 0; i < LP - 1; i++) {
      int ev = __ldg(e + i);
      ev = ev < 0 ? 0 : (ev > NE - 1 ? NE - 1 : ev);
      w[i] = __ldg(weight + ev);
    }
  }

  const int col = lane * 4;
  uint2 ra[LP - 1], rb[LP - 1];
#pragma unroll
  for (int i = 0; i < LP - 1; i++) {
    ra[i] = __ldg((const uint2*)(g_proj + (size_t)idx[i] * PROJ_COLS + i * DP + col));
    rb[i] = __ldg((const uint2*)(g_proj + (size_t)idx[i + 1] * PROJ_COLS + i * DP + col));
  }

  float4 acc = make_float4(0.f, 0.f, 0.f, 0.f);
#pragma unroll
  for (int i = 0; i < LP - 1; i++) {
    float2 a01 = __half22float2(*(const __half2*)&ra[i].x);
    float2 a23 = __half22float2(*(const __half2*)&ra[i].y);
    float2 b01 = __half22float2(*(const __half2*)&rb[i].x);
    float2 b23 = __half22float2(*(const __half2*)&rb[i].y);
    acc.x += a01.x + w[i] * b01.x;
    acc.y += a01.y + w[i] * b01.y;
    acc.z += a23.x + w[i] * b23.x;
    acc.w += a23.y + w[i] * b23.y;
  }
  // streaming store: evict-first, keep proj resident in L2
  float* dst = out + gw * DP + col;
  asm volatile("st.global.cs.v4.f32 [%0], {%1,%2,%3,%4};"
               :: "l"(dst), "f"(acc.x), "f"(acc.y), "f"(acc.z), "f"(acc.w)
               : "memory");
}

// ---------------------------------------------------------------------------
// Launch. Inputs identified BY ELEMENT COUNT (all five distinct):
//   feat=3,200,000 f32 | weight=1,600,000 f32 | W=40,960 f32
//   paths=2,400,000 (i32/i64) | edge_ids=2,000,000 (i32/i64)
// ---------------------------------------------------------------------------
extern "C" void kernel_launch(void* const* d_in, const int* in_sizes, int n_in,
                              void* d_out, int out_size) {
  const float* feat = 0;
  const float* weight = 0;
  const float* W = 0;
  const void* paths = 0;
  const void* eids = 0;

  for (int i = 0; i < n_in; i++) {
    switch (in_sizes[i]) {
      case 3200000: feat   = (const float*)d_in[i]; break;
      case 1600000: weight = (const float*)d_in[i]; break;
      case 40960:   W      = (const float*)d_in[i]; break;
      case 2400000: paths  = d_in[i];               break;
      case 2000000: eids   = d_in[i];               break;
      default: break;
    }
  }
  if (!feat || !weight || !W || !paths || !eids) return;

  float* out = (float*)d_out;

  dim3 g1((NN + 1 + 127) / 128, 5);   // 391 x 5 CTAs, one l block per y
  phase1_mma<<<g1, 256>>>(feat, W, (const unsigned int*)paths);

  long long warps = (long long)NN * KP;               // 400,000
  int blocks = (int)((warps * 32 + 255) / 256);       // 50,000
  phase2_gather<<<blocks, 256>>>(paths, eids, weight, out);
}

// round 11
// speedup vs baseline: 1.7895x; 1.0400x over previous
#include <cuda_runtime.h>
#include <cuda_fp16.h>

#define NN 50000         // n_node
#define KP 8             // k_path
#define LP 6             // l_path
#define DN 64            // d_node
#define DP 128           // d_path
#define NE 1600000       // n_edge
#define PROJ_COLS 640    // (LP-1) * DP

// fp16 proj table (64 MB, L2-resident). proj[node][l*128+d]; row NN = zeros.
__device__ __half g_proj[(size_t)(NN + 1) * PROJ_COLS];
__device__ int g_is64;

// ---------------------------------------------------------------------------
// Phase 1 (tensor-core): proj[node][l*128+d] = sum_c feat16[node,c] * W16[d, l*64+c]
// Per CTA: 128 nodes (M) x 128 d (N), K=64, one l block (blockIdx.y).
// Block (0,0) warp 0 additionally sniffs the index dtype into g_is64.
// ---------------------------------------------------------------------------
#define TS 72   // smem row stride in halves (64 + 8 pad) -> conflict-free frags

__global__ void __launch_bounds__(256, 2) phase1_mma(
    const float* __restrict__ feat, const float* __restrict__ W,
    const unsigned int* __restrict__ paths_raw) {
  __shared__ __half As[128 * TS];   // [node][c]
  __shared__ __half Bs[128 * TS];   // [d][c]

  const int t = threadIdx.x;
  const int node0 = blockIdx.x * 128;
  const int l = blockIdx.y;

  // ---- dtype sniff (one warp, one block): int64 data has all-zero high words ----
  if (blockIdx.x == 0 && blockIdx.y == 0 && t < 32) {
    unsigned v = paths_raw[t * 2 + 1];
    unsigned any = __ballot_sync(0xFFFFFFFFu, v != 0u);
    if (t == 0) g_is64 = (any == 0u) ? 1 : 0;
  }

  // ---- load + convert A tile: 128 nodes x 64 c (2048 float4, 8 per thread) ----
#pragma unroll
  for (int i = 0; i < 8; i++) {
    int f4 = t + 256 * i;
    int row = f4 >> 4;              // local node row 0..127
    int c4 = (f4 & 15) * 4;
    int node = node0 + row;
    float4 v = make_float4(0.f, 0.f, 0.f, 0.f);
    if (node < NN) v = *(const float4*)(feat + (size_t)node * DN + c4);
    __half2 h0 = __floats2half2_rn(v.x, v.y);
    __half2 h1 = __floats2half2_rn(v.z, v.w);
    uint2 pk;
    pk.x = *(unsigned*)&h0;
    pk.y = *(unsigned*)&h1;
    *(uint2*)(As + row * TS + c4) = pk;
  }
  // ---- load + convert B tile: 128 d x 64 c from W[d][320] slice [l*64, l*64+64) ----
#pragma unroll
  for (int i = 0; i < 8; i++) {
    int f4 = t + 256 * i;
    int d = f4 >> 4;
    int c4 = (f4 & 15) * 4;
    float4 v = *(const float4*)(W + (size_t)d * 320 + l * 64 + c4);
    __half2 h0 = __floats2half2_rn(v.x, v.y);
    __half2 h1 = __floats2half2_rn(v.z, v.w);
    uint2 pk;
    pk.x = *(unsigned*)&h0;
    pk.y = *(unsigned*)&h1;
    *(uint2*)(Bs + d * TS + c4) = pk;
  }
  __syncthreads();

  const int lane = t & 31;
  const int wid = t >> 5;
  const int m0 = (wid >> 1) * 32;   // node dim
  const int n0 = (wid & 1) * 64;    // d dim
  const int grp = lane >> 2;
  const int tig = lane & 3;

  float acc[2][8][4];
#pragma unroll
  for (int a = 0; a < 2; a++)
#pragma unroll
    for (int b = 0; b < 8; b++)
#pragma unroll
      for (int c = 0; c < 4; c++) acc[a][b][c] = 0.f;

#pragma unroll
  for (int ks = 0; ks < 4; ks++) {
    unsigned afr[2][4];
#pragma unroll
    for (int mt = 0; mt < 2; mt++) {
      const __half* ap = As + (size_t)(m0 + mt * 16 + grp) * TS + ks * 16 + tig * 2;
      afr[mt][0] = *(const unsigned*)(ap);
      afr[mt][1] = *(const unsigned*)(ap + 8 * TS);
      afr[mt][2] = *(const unsigned*)(ap + 8);
      afr[mt][3] = *(const unsigned*)(ap + 8 * TS + 8);
    }
#pragma unroll
    for (int nt = 0; nt < 8; nt++) {
      const __half* bp = Bs + (size_t)(n0 + nt * 8 + grp) * TS + ks * 16 + tig * 2;
      unsigned b0 = *(const unsigned*)(bp);
      unsigned b1 = *(const unsigned*)(bp + 8);
#pragma unroll
      for (int mt = 0; mt < 2; mt++)
        asm volatile(
            "mma.sync.aligned.m16n8k16.row.col.f32.f16.f16.f32 "
            "{%0,%1,%2,%3}, {%4,%5,%6,%7}, {%8,%9}, {%0,%1,%2,%3};"
            : "+f"(acc[mt][nt][0]), "+f"(acc[mt][nt][1]),
              "+f"(acc[mt][nt][2]), "+f"(acc[mt][nt][3])
            : "r"(afr[mt][0]), "r"(afr[mt][1]), "r"(afr[mt][2]), "r"(afr[mt][3]),
              "r"(b0), "r"(b1));
    }
  }

  // ---- epilogue: half2 stores straight to the proj table ----
#pragma unroll
  for (int mt = 0; mt < 2; mt++) {
    int nodeA = node0 + m0 + mt * 16 + grp;
    int nodeB = nodeA + 8;
#pragma unroll
    for (int nt = 0; nt < 8; nt++) {
      int d = n0 + nt * 8 + tig * 2;
      if (nodeA <= NN) {
        __half2 h = __floats2half2_rn(acc[mt][nt][0], acc[mt][nt][1]);
        *(__half2*)(g_proj + (size_t)nodeA * PROJ_COLS + l * DP + d) = h;
      }
      if (nodeB <= NN) {
        __half2 h = __floats2half2_rn(acc[mt][nt][2], acc[mt][nt][3]);
        *(__half2*)(g_proj + (size_t)nodeB * PROJ_COLS + l * DP + d) = h;
      }
    }
  }
}

// ---------------------------------------------------------------------------
// Phase 2: one warp per (n,k).
//  - index/weight prologue parallelized across lanes (2 load steps, not 11)
//  - proj/weight gathers use a createpolicy evict_last cache hint
//  - out uses streaming evict-first stores
// ---------------------------------------------------------------------------
__device__ __forceinline__ unsigned long long make_evict_last_policy() {
  unsigned long long pol;
  asm("createpolicy.fractional.L2::evict_last.b64 %0, 1.0;" : "=l"(pol));
  return pol;
}

__device__ __forceinline__ uint2 ldg_el_u2(const void* p, unsigned long long pol) {
  uint2 r;
  asm volatile("ld.global.nc.L2::cache_hint.v2.u32 {%0,%1}, [%2], %3;"
               : "=r"(r.x), "=r"(r.y) : "l"(p), "l"(pol));
  return r;
}

__global__ void __launch_bounds__(256) phase2_gather(
    const void* __restrict__ paths_v,
    const void* __restrict__ eids_v,
    const float* __restrict__ weight,
    float* __restrict__ out) {
  const long long gw = (((long long)blockIdx.x * blockDim.x) + threadIdx.x) >> 5;
  const int lane = threadIdx.x & 31;
  if (gw >= (long long)NN * KP) return;

  const int is64 = g_is64;
  const unsigned long long pol = make_evict_last_policy();

  // ---- parallel prologue: lanes 0..5 -> path ids, lanes 6..10 -> edge+weight ----
  int pv = 0;
  float wv = 0.f;
  if (is64) {
    if (lane < LP) {
      long long v = __ldg((const long long*)paths_v + gw * LP + lane);
      v = v < 0 ? 0 : (v > NN ? NN : v);
      pv = (int)v;
    } else if (lane < LP + LP - 1) {
      long long ev = __ldg((const long long*)eids_v + gw * (LP - 1) + (lane - LP));
      ev = ev < 0 ? 0 : (ev > NE - 1 ? NE - 1 : ev);
      float t;
      asm volatile("ld.global.nc.L2::cache_hint.f32 %0, [%1], %2;"
                   : "=f"(t) : "l"(weight + ev), "l"(pol));
      wv = t;
    }
  } else {
    if (lane < LP) {
      int v = __ldg((const int*)paths_v + gw * LP + lane);
      v = v < 0 ? 0 : (v > NN ? NN : v);
      pv = v;
    } else if (lane < LP + LP - 1) {
      int ev = __ldg((const int*)eids_v + gw * (LP - 1) + (lane - LP));
      ev = ev < 0 ? 0 : (ev > NE - 1 ? NE - 1 : ev);
      float t;
      asm volatile("ld.global.nc.L2::cache_hint.f32 %0, [%1], %2;"
                   : "=f"(t) : "l"(weight + ev), "l"(pol));
      wv = t;
    }
  }

  int idx[LP];
  float w[LP - 1];
#pragma unroll
  for (int i = 0; i < LP; i++) idx[i] = __shfl_sync(0xFFFFFFFFu, pv, i);
#pragma unroll
  for (int i = 0; i < LP - 1; i++) w[i] = __shfl_sync(0xFFFFFFFFu, wv, LP + i);

  // ---- gather 10 proj vectors (8 B/lane each) with evict_last hint ----
  const int col = lane * 4;
  uint2 ra[LP - 1], rb[LP - 1];
#pragma unroll
  for (int i = 0; i < LP - 1; i++) {
    ra[i] = ldg_el_u2(g_proj + (size_t)idx[i] * PROJ_COLS + i * DP + col, pol);
    rb[i] = ldg_el_u2(g_proj + (size_t)idx[i + 1] * PROJ_COLS + i * DP + col, pol);
  }

  float4 acc = make_float4(0.f, 0.f, 0.f, 0.f);
#pragma unroll
  for (int i = 0; i < LP - 1; i++) {
    float2 a01 = __half22float2(*(const __half2*)&ra[i].x);
    float2 a23 = __half22float2(*(const __half2*)&ra[i].y);
    float2 b01 = __half22float2(*(const __half2*)&rb[i].x);
    float2 b23 = __half22float2(*(const __half2*)&rb[i].y);
    acc.x += a01.x + w[i] * b01.x;
    acc.y += a01.y + w[i] * b01.y;
    acc.z += a23.x + w[i] * b23.x;
    acc.w += a23.y + w[i] * b23.y;
  }
  // streaming store: evict-first, keep proj resident in L2
  float* dst = out + gw * DP + col;
  asm volatile("st.global.cs.v4.f32 [%0], {%1,%2,%3,%4};"
               :: "l"(dst), "f"(acc.x), "f"(acc.y), "f"(acc.z), "f"(acc.w)
               : "memory");
}

// ---------------------------------------------------------------------------
// Launch. Inputs identified BY ELEMENT COUNT (all five distinct):
//   feat=3,200,000 f32 | weight=1,600,000 f32 | W=40,960 f32
//   paths=2,400,000 (i32/i64) | edge_ids=2,000,000 (i32/i64)
// ---------------------------------------------------------------------------
extern "C" void kernel_launch(void* const* d_in, const int* in_sizes, int n_in,
                              void* d_out, int out_size) {
  const float* feat = 0;
  const float* weight = 0;
  const float* W = 0;
  const void* paths = 0;
  const void* eids = 0;

  for (int i = 0; i < n_in; i++) {
    switch (in_sizes[i]) {
      case 3200000: feat   = (const float*)d_in[i]; break;
      case 1600000: weight = (const float*)d_in[i]; break;
      case 40960:   W      = (const float*)d_in[i]; break;
      case 2400000: paths  = d_in[i];               break;
      case 2000000: eids   = d_in[i];               break;
      default: break;
    }
  }
  if (!feat || !weight || !W || !paths || !eids) return;

  float* out = (float*)d_out;

  dim3 g1((NN + 1 + 127) / 128, 5);   // 391 x 5 CTAs, one l block per y
  phase1_mma<<<g1, 256>>>(feat, W, (const unsigned int*)paths);

  long long warps = (long long)NN * KP;               // 400,000
  int blocks = (int)((warps * 32 + 255) / 256);       // 50,000
  phase2_gather<<<blocks, 256>>>(paths, eids, weight, out);
}